// round 4
// baseline (speedup 1.0000x reference)
#include <cuda_runtime.h>

#define NN 100000
#define EE 3200000
#define F  16

// ---------------- device scratch (no allocations) ----------------
__device__ int      g_cnt[NN];
__device__ float    g_dinv[NN];
__device__ float    g_A[NN * F];   // transformed features (h @ W)
__device__ float    g_B[NN * F];   // edge-aggregation accumulator
__device__ float    g_C[NN * F];   // layer output h
__device__ float    g_c1[NN];      // h2 @ W3
__device__ float    g_c2a[NN];     // scalar agg accumulator
__device__ float    g_c2[NN];      // logits
__device__ float    g_sum16[F];
__device__ unsigned g_maxkey;
__device__ float    g_gmax;
__device__ double   g_sumexp;
__device__ int      g_cmode;       // 0=int32, 1=float32, 2=bool8

// ---------------- helpers ----------------
__device__ __forceinline__ unsigned fkey(float f) {
    unsigned u = __float_as_uint(f);
    return (u & 0x80000000u) ? ~u : (u | 0x80000000u);
}
__device__ __forceinline__ float fdec(unsigned k) {
    unsigned u = (k & 0x80000000u) ? (k ^ 0x80000000u) : ~k;
    return __uint_as_float(u);
}
__device__ __forceinline__ bool chosen(const void* p, int i) {
    int m = g_cmode;
    if (m == 0) return ((const int*)p)[i] != 0;
    if (m == 1) return ((const float*)p)[i] != 0.0f;
    return ((const unsigned char*)p)[i] != 0;
}

// ---------------- kernels ----------------
__global__ void k_init(int n) {
    int i = blockIdx.x * blockDim.x + threadIdx.x;
    if (i < n) g_cnt[i] = 0;
    if (blockIdx.x == 0) {
        if (threadIdx.x < F) g_sum16[threadIdx.x] = 0.0f;
        if (threadIdx.x == 0) { g_maxkey = 0u; g_sumexp = 0.0; }
    }
}

__global__ void k_detect(const unsigned int* __restrict__ w, int nw) {
    __shared__ int notI, notF;
    if (threadIdx.x == 0) { notI = 0; notF = 0; }
    __syncthreads();
    int li = 0, lf = 0;
    for (int i = threadIdx.x; i < nw; i += blockDim.x) {
        unsigned v = w[i];
        li |= (v > 1u);
        lf |= (v != 0u && v != 0x3F800000u);
    }
    if (li) notI = 1;
    if (lf) notF = 1;
    __syncthreads();
    if (threadIdx.x == 0) g_cmode = (!notI) ? 0 : ((!notF) ? 1 : 2);
}

__global__ void k_deg(const int* __restrict__ col, int e) {
    int i = blockIdx.x * blockDim.x + threadIdx.x;
    if (i < e) atomicAdd(&g_cnt[col[i]], 1);
}

__global__ void k_dinv(int n) {
    int i = blockIdx.x * blockDim.x + threadIdx.x;
    if (i < n) g_dinv[i] = rsqrtf((float)g_cnt[i] + 2.0f);
}

__global__ void k_xw1(const float* __restrict__ x, const float* __restrict__ W1, int n) {
    int idx = blockIdx.x * blockDim.x + threadIdx.x;
    if (idx >= n * F) return;
    int i = idx >> 4, f = idx & 15;
    float v = x[i * 3 + 0] * __ldg(&W1[0 * F + f])
            + x[i * 3 + 1] * __ldg(&W1[1 * F + f])
            + x[i * 3 + 2] * __ldg(&W1[2 * F + f]);
    g_A[idx] = v;
}

__global__ void k_zeroB(int cnt) {
    int i = blockIdx.x * blockDim.x + threadIdx.x;
    if (i < cnt) g_B[i] = 0.0f;
}
__global__ void k_zeroC2a(int n) {
    int i = blockIdx.x * blockDim.x + threadIdx.x;
    if (i < n) g_c2a[i] = 0.0f;
}

// literal transcription of reference: scatter A[row]*dinv[row]*dinv[col] into B[col]
__global__ void k_scatter16(const int* __restrict__ row, const int* __restrict__ col, int e) {
    long long idx = (long long)blockIdx.x * blockDim.x + threadIdx.x;
    if (idx >= (long long)e * F) return;
    int ed = (int)(idx >> 4), f = (int)(idx & 15);
    int r = row[ed], c = col[ed];
    float enorm = g_dinv[r] * g_dinv[c];
    atomicAdd(&g_B[c * F + f], g_A[r * F + f] * enorm);
}

__global__ void k_combine16(const float* __restrict__ b, int n, int relu) {
    int idx = blockIdx.x * blockDim.x + threadIdx.x;
    if (idx >= n * F) return;
    int i = idx >> 4, f = idx & 15;
    float di = g_dinv[i];
    float v = g_B[idx] + 2.0f * di * di * g_A[idx] + __ldg(&b[f]);
    if (relu) v = fmaxf(v, 0.0f);
    g_C[idx] = v;
}

__global__ void k_dense16(const float* __restrict__ W, int n) {
    __shared__ float sW[256];
    sW[threadIdx.x] = W[threadIdx.x];
    __syncthreads();
    int idx = blockIdx.x * blockDim.x + threadIdx.x;
    if (idx >= n * F) return;
    int i = idx >> 4, f = idx & 15;
    float acc = 0.0f;
#pragma unroll
    for (int k = 0; k < F; k++) acc += g_C[i * F + k] * sW[k * F + f];
    g_A[idx] = acc;
}

__global__ void k_densecol(const float* __restrict__ W3, int n) {
    int i = blockIdx.x * blockDim.x + threadIdx.x;
    if (i >= n) return;
    float acc = 0.0f;
#pragma unroll
    for (int k = 0; k < F; k++) acc += g_C[i * F + k] * __ldg(&W3[k]);
    g_c1[i] = acc;
}

__global__ void k_scatter1(const int* __restrict__ row, const int* __restrict__ col, int e) {
    int ed = blockIdx.x * blockDim.x + threadIdx.x;
    if (ed >= e) return;
    int r = row[ed], c = col[ed];
    atomicAdd(&g_c2a[c], g_c1[r] * g_dinv[r] * g_dinv[c]);
}

__global__ void k_combine1(const float* __restrict__ b3, int n) {
    int i = blockIdx.x * blockDim.x + threadIdx.x;
    if (i >= n) return;
    float di = g_dinv[i];
    g_c2[i] = g_c2a[i] + 2.0f * di * di * g_c1[i] + __ldg(&b3[0]);
}

// masked max of logits + column sums of h2 (= g_C)
__global__ void k_reduce1(const void* __restrict__ ch, int n) {
    int idx = blockIdx.x * blockDim.x + threadIdx.x;
    int stride = gridDim.x * blockDim.x;  // multiple of 16
    float sacc = 0.0f;
    for (int j = idx; j < n * F; j += stride) sacc += g_C[j];
    sacc += __shfl_down_sync(0xFFFFFFFFu, sacc, 16);
    if ((threadIdx.x & 31) < 16) atomicAdd(&g_sum16[idx & 15], sacc);

    float lmax = -3.0e38f;
    for (int i = idx; i < n; i += stride)
        if (chosen(ch, i)) lmax = fmaxf(lmax, g_c2[i]);
#pragma unroll
    for (int o = 16; o; o >>= 1) lmax = fmaxf(lmax, __shfl_down_sync(0xFFFFFFFFu, lmax, o));
    if ((threadIdx.x & 31) == 0) atomicMax(&g_maxkey, fkey(lmax));
}

__global__ void k_fin1(float* out, const float* __restrict__ fc_w,
                       const float* __restrict__ fc_b, int n, int out_size) {
    int t = threadIdx.x;
    float p = 0.0f;
    if (t < F) p = (g_sum16[t] / (float)n) * __ldg(&fc_w[t]);
#pragma unroll
    for (int o = 8; o; o >>= 1) p += __shfl_down_sync(0xFFFFFFFFu, p, o);
    if (t == 0) {
        g_gmax = fdec(g_maxkey);
        if (out_size > n) out[n] = p + __ldg(&fc_b[0]);
    }
}

__global__ void k_sumexp(const void* __restrict__ ch, int n) {
    int idx = blockIdx.x * blockDim.x + threadIdx.x;
    int stride = gridDim.x * blockDim.x;
    float gmax = g_gmax;
    double ls = 0.0;
    for (int i = idx; i < n; i += stride)
        if (chosen(ch, i)) ls += (double)expf(g_c2[i] - gmax);
#pragma unroll
    for (int o = 16; o; o >>= 1) ls += __shfl_down_sync(0xFFFFFFFFu, ls, o);
    if ((threadIdx.x & 31) == 0) atomicAdd(&g_sumexp, ls);
}

__global__ void k_writeout(float* __restrict__ out, const void* __restrict__ ch, int n) {
    int i = blockIdx.x * blockDim.x + threadIdx.x;
    if (i >= n) return;
    float v = 0.0f;
    if (chosen(ch, i)) v = expf(g_c2[i] - g_gmax) / (float)g_sumexp;
    out[i] = v;
}

// ---------------- launch ----------------
extern "C" void kernel_launch(void* const* d_in, const int* in_sizes, int n_in,
                              void* d_out, int out_size) {
    const float* x    = (const float*)d_in[0];
    const int*   ei   = (const int*)d_in[1];
    const void*  ch   = (const void*)d_in[2];
    const float* W1   = (const float*)d_in[3];
    const float* b1   = (const float*)d_in[4];
    const float* W2   = (const float*)d_in[5];
    const float* b2   = (const float*)d_in[6];
    const float* W3   = (const float*)d_in[7];
    const float* b3   = (const float*)d_in[8];
    const float* fc_w = (const float*)d_in[9];
    const float* fc_b = (const float*)d_in[10];
    float* out = (float*)d_out;

    int n = in_sizes[0] / 3;
    int e = in_sizes[1] / 2;
    if (n > NN) n = NN;
    if (e > EE) e = EE;
    const int* row = ei;       // edge_index[0] = source
    const int* col = ei + e;   // edge_index[1] = target

    int bn   = (n + 255) / 256;
    int be   = (e + 255) / 256;
    int bnf  = (n * F + 255) / 256;
    int bef  = (int)(((long long)e * F + 255) / 256);

    k_init<<<bn, 256>>>(n);
    k_detect<<<1, 256>>>((const unsigned int*)ch, n / 4);
    k_deg<<<be, 256>>>(col, e);
    k_dinv<<<bn, 256>>>(n);

    // layer 1
    k_xw1<<<bnf, 256>>>(x, W1, n);
    k_zeroB<<<bnf, 256>>>(n * F);
    k_scatter16<<<bef, 256>>>(row, col, e);
    k_combine16<<<bnf, 256>>>(b1, n, 1);

    // layer 2
    k_dense16<<<bnf, 256>>>(W2, n);
    k_zeroB<<<bnf, 256>>>(n * F);
    k_scatter16<<<bef, 256>>>(row, col, e);
    k_combine16<<<bnf, 256>>>(b2, n, 1);

    // layer 3 (scalar)
    k_densecol<<<bn, 256>>>(W3, n);
    k_zeroC2a<<<bn, 256>>>(n);
    k_scatter1<<<be, 256>>>(row, col, e);
    k_combine1<<<bn, 256>>>(b3, n);

    // heads
    k_reduce1<<<512, 256>>>(ch, n);
    k_fin1<<<1, 32>>>(out, fc_w, fc_b, n, out_size);
    k_sumexp<<<512, 256>>>(ch, n);
    k_writeout<<<bn, 256>>>(out, ch, n);
}

// round 6
// speedup vs baseline: 1.3179x; 1.3179x over previous
#include <cuda_runtime.h>

#define NN 100000
#define EE 3200000
#define F  16

// ---------------- device scratch (no allocations) ----------------
__device__ int      g_cnt[NN];
__device__ float    g_dinv[NN];
__device__ float    g_A[NN * F];   // transformed features (h @ W)
__device__ float    g_B[NN * F];   // edge-aggregation accumulator
__device__ float    g_C[NN * F];   // layer output h
__device__ float    g_c1[NN];      // h2 @ W3
__device__ float    g_c2a[NN];     // scalar agg accumulator
__device__ float    g_c2[NN];      // logits
__device__ float    g_sum16[F];
__device__ unsigned g_maxkey;
__device__ float    g_gmax;
__device__ double   g_sumexp;
__device__ int      g_cmode;       // 0=int32, 1=float32, 2=bool8

// ---------------- helpers ----------------
__device__ __forceinline__ unsigned fkey(float f) {
    unsigned u = __float_as_uint(f);
    return (u & 0x80000000u) ? ~u : (u | 0x80000000u);
}
__device__ __forceinline__ float fdec(unsigned k) {
    unsigned u = (k & 0x80000000u) ? (k ^ 0x80000000u) : ~k;
    return __uint_as_float(u);
}
__device__ __forceinline__ bool chosen(const void* p, int i) {
    int m = g_cmode;
    if (m == 0) return ((const int*)p)[i] != 0;
    if (m == 1) return ((const float*)p)[i] != 0.0f;
    return ((const unsigned char*)p)[i] != 0;
}
__device__ __forceinline__ void red_add_v4(float* p, float4 v) {
    asm volatile("red.global.add.v4.f32 [%0], {%1, %2, %3, %4};"
                 :: "l"(p), "f"(v.x), "f"(v.y), "f"(v.z), "f"(v.w) : "memory");
}

// ---------------- kernels ----------------
__global__ void k_init(int n) {
    int i = blockIdx.x * blockDim.x + threadIdx.x;
    if (i < n) g_cnt[i] = 0;
    if (blockIdx.x == 0) {
        if (threadIdx.x < F) g_sum16[threadIdx.x] = 0.0f;
        if (threadIdx.x == 0) { g_maxkey = 0u; g_sumexp = 0.0; }
    }
}

__global__ void k_detect(const unsigned int* __restrict__ w, int nw) {
    __shared__ int notI, notF;
    if (threadIdx.x == 0) { notI = 0; notF = 0; }
    __syncthreads();
    int li = 0, lf = 0;
    for (int i = threadIdx.x; i < nw; i += blockDim.x) {
        unsigned v = w[i];
        li |= (v > 1u);
        lf |= (v != 0u && v != 0x3F800000u);
    }
    if (li) notI = 1;
    if (lf) notF = 1;
    __syncthreads();
    if (threadIdx.x == 0) g_cmode = (!notI) ? 0 : ((!notF) ? 1 : 2);
}

__global__ void k_deg(const int* __restrict__ col, int e) {
    int i = blockIdx.x * blockDim.x + threadIdx.x;
    if (i < e) atomicAdd(&g_cnt[col[i]], 1);
}

__global__ void k_dinv(int n) {
    int i = blockIdx.x * blockDim.x + threadIdx.x;
    if (i < n) g_dinv[i] = rsqrtf((float)g_cnt[i] + 2.0f);
}

__global__ void k_xw1(const float* __restrict__ x, const float* __restrict__ W1, int n) {
    int idx = blockIdx.x * blockDim.x + threadIdx.x;
    if (idx >= n * F) return;
    int i = idx >> 4, f = idx & 15;
    float v = x[i * 3 + 0] * __ldg(&W1[0 * F + f])
            + x[i * 3 + 1] * __ldg(&W1[1 * F + f])
            + x[i * 3 + 2] * __ldg(&W1[2 * F + f]);
    g_A[idx] = v;
}

__global__ void k_zeroB(int cnt) {
    int i = blockIdx.x * blockDim.x + threadIdx.x;
    if (i < cnt) g_B[i] = 0.0f;
}
__global__ void k_zeroC2a(int n) {
    int i = blockIdx.x * blockDim.x + threadIdx.x;
    if (i < n) g_c2a[i] = 0.0f;
}

// THE ONLY CHANGE vs round 4: 4 threads/edge, one red.v4 (16B) each,
// same math: B[c] += A[r] * dinv[r] * dinv[c]
__global__ void k_scatter16(const int* __restrict__ row, const int* __restrict__ col, int e) {
    int gid = blockIdx.x * blockDim.x + threadIdx.x;
    int ed = gid >> 2;
    if (ed >= e) return;
    int q = gid & 3;
    int r = __ldg(&row[ed]);
    int c = __ldg(&col[ed]);
    float enorm = g_dinv[r] * g_dinv[c];
    float4 v = *(const float4*)&g_A[r * F + q * 4];
    v.x *= enorm; v.y *= enorm; v.z *= enorm; v.w *= enorm;
    red_add_v4(&g_B[c * F + q * 4], v);
}

__global__ void k_combine16(const float* __restrict__ b, int n, int relu) {
    int idx = blockIdx.x * blockDim.x + threadIdx.x;
    if (idx >= n * F) return;
    int i = idx >> 4, f = idx & 15;
    float di = g_dinv[i];
    float v = g_B[idx] + 2.0f * di * di * g_A[idx] + __ldg(&b[f]);
    if (relu) v = fmaxf(v, 0.0f);
    g_C[idx] = v;
}

__global__ void k_dense16(const float* __restrict__ W, int n) {
    __shared__ float sW[256];
    sW[threadIdx.x] = W[threadIdx.x];
    __syncthreads();
    int idx = blockIdx.x * blockDim.x + threadIdx.x;
    if (idx >= n * F) return;
    int i = idx >> 4, f = idx & 15;
    float acc = 0.0f;
#pragma unroll
    for (int k = 0; k < F; k++) acc += g_C[i * F + k] * sW[k * F + f];
    g_A[idx] = acc;
}

__global__ void k_densecol(const float* __restrict__ W3, int n) {
    int i = blockIdx.x * blockDim.x + threadIdx.x;
    if (i >= n) return;
    float acc = 0.0f;
#pragma unroll
    for (int k = 0; k < F; k++) acc += g_C[i * F + k] * __ldg(&W3[k]);
    g_c1[i] = acc;
}

__global__ void k_scatter1(const int* __restrict__ row, const int* __restrict__ col, int e) {
    int ed = blockIdx.x * blockDim.x + threadIdx.x;
    if (ed >= e) return;
    int r = row[ed], c = col[ed];
    atomicAdd(&g_c2a[c], g_c1[r] * g_dinv[r] * g_dinv[c]);
}

__global__ void k_combine1(const float* __restrict__ b3, int n) {
    int i = blockIdx.x * blockDim.x + threadIdx.x;
    if (i >= n) return;
    float di = g_dinv[i];
    g_c2[i] = g_c2a[i] + 2.0f * di * di * g_c1[i] + __ldg(&b3[0]);
}

__global__ void k_reduce1(const void* __restrict__ ch, int n) {
    int idx = blockIdx.x * blockDim.x + threadIdx.x;
    int stride = gridDim.x * blockDim.x;  // multiple of 16
    float sacc = 0.0f;
    for (int j = idx; j < n * F; j += stride) sacc += g_C[j];
    sacc += __shfl_down_sync(0xFFFFFFFFu, sacc, 16);
    if ((threadIdx.x & 31) < 16) atomicAdd(&g_sum16[idx & 15], sacc);

    float lmax = -3.0e38f;
    for (int i = idx; i < n; i += stride)
        if (chosen(ch, i)) lmax = fmaxf(lmax, g_c2[i]);
#pragma unroll
    for (int o = 16; o; o >>= 1) lmax = fmaxf(lmax, __shfl_down_sync(0xFFFFFFFFu, lmax, o));
    if ((threadIdx.x & 31) == 0) atomicMax(&g_maxkey, fkey(lmax));
}

__global__ void k_fin1(float* out, const float* __restrict__ fc_w,
                       const float* __restrict__ fc_b, int n, int out_size) {
    int t = threadIdx.x;
    float p = 0.0f;
    if (t < F) p = (g_sum16[t] / (float)n) * __ldg(&fc_w[t]);
#pragma unroll
    for (int o = 8; o; o >>= 1) p += __shfl_down_sync(0xFFFFFFFFu, p, o);
    if (t == 0) {
        g_gmax = fdec(g_maxkey);
        if (out_size > n) out[n] = p + __ldg(&fc_b[0]);
    }
}

__global__ void k_sumexp(const void* __restrict__ ch, int n) {
    int idx = blockIdx.x * blockDim.x + threadIdx.x;
    int stride = gridDim.x * blockDim.x;
    float gmax = g_gmax;
    double ls = 0.0;
    for (int i = idx; i < n; i += stride)
        if (chosen(ch, i)) ls += (double)expf(g_c2[i] - gmax);
#pragma unroll
    for (int o = 16; o; o >>= 1) ls += __shfl_down_sync(0xFFFFFFFFu, ls, o);
    if ((threadIdx.x & 31) == 0) atomicAdd(&g_sumexp, ls);
}

__global__ void k_writeout(float* __restrict__ out, const void* __restrict__ ch, int n) {
    int i = blockIdx.x * blockDim.x + threadIdx.x;
    if (i >= n) return;
    float v = 0.0f;
    if (chosen(ch, i)) v = expf(g_c2[i] - g_gmax) / (float)g_sumexp;
    out[i] = v;
}

// ---------------- launch ----------------
extern "C" void kernel_launch(void* const* d_in, const int* in_sizes, int n_in,
                              void* d_out, int out_size) {
    const float* x    = (const float*)d_in[0];
    const int*   ei   = (const int*)d_in[1];
    const void*  ch   = (const void*)d_in[2];
    const float* W1   = (const float*)d_in[3];
    const float* b1   = (const float*)d_in[4];
    const float* W2   = (const float*)d_in[5];
    const float* b2   = (const float*)d_in[6];
    const float* W3   = (const float*)d_in[7];
    const float* b3   = (const float*)d_in[8];
    const float* fc_w = (const float*)d_in[9];
    const float* fc_b = (const float*)d_in[10];
    float* out = (float*)d_out;

    int n = in_sizes[0] / 3;
    int e = in_sizes[1] / 2;
    if (n > NN) n = NN;
    if (e > EE) e = EE;
    const int* row = ei;       // edge_index[0] = source
    const int* col = ei + e;   // edge_index[1] = target

    int bn   = (n + 255) / 256;
    int be   = (e + 255) / 256;
    int bnf  = (n * F + 255) / 256;
    int bs4  = (int)(((long long)e * 4 + 255) / 256);  // 4 threads per edge

    k_init<<<bn, 256>>>(n);
    k_detect<<<1, 256>>>((const unsigned int*)ch, n / 4);
    k_deg<<<be, 256>>>(col, e);
    k_dinv<<<bn, 256>>>(n);

    // layer 1
    k_xw1<<<bnf, 256>>>(x, W1, n);
    k_zeroB<<<bnf, 256>>>(n * F);
    k_scatter16<<<bs4, 256>>>(row, col, e);
    k_combine16<<<bnf, 256>>>(b1, n, 1);

    // layer 2
    k_dense16<<<bnf, 256>>>(W2, n);
    k_zeroB<<<bnf, 256>>>(n * F);
    k_scatter16<<<bs4, 256>>>(row, col, e);
    k_combine16<<<bnf, 256>>>(b2, n, 1);

    // layer 3 (scalar)
    k_densecol<<<bn, 256>>>(W3, n);
    k_zeroC2a<<<bn, 256>>>(n);
    k_scatter1<<<be, 256>>>(row, col, e);
    k_combine1<<<bn, 256>>>(b3, n);

    // heads
    k_reduce1<<<512, 256>>>(ch, n);
    k_fin1<<<1, 32>>>(out, fc_w, fc_b, n, out_size);
    k_sumexp<<<512, 256>>>(ch, n);
    k_writeout<<<bn, 256>>>(out, ch, n);
}

// round 7
// speedup vs baseline: 1.7259x; 1.3096x over previous
#include <cuda_runtime.h>

#define NN 100000
#define EE 3200000
#define F  16

// ---------------- device scratch (no allocations) ----------------
// RULE: these are referenced BY NAME inside kernels only — never passed
// as kernel arguments from host code (host sees only shadow symbols).
__device__ int      g_cnt[NN];
__device__ float    g_dinv[NN];
__device__ float    g_P1[NN * F];   // (x@W1)*dinv
__device__ float    g_B1[NN * F];   // layer-1 edge accumulator
__device__ float    g_P2[NN * F];   // (h1@W2)*dinv
__device__ float    g_B2[NN * F];   // layer-2 edge accumulator
__device__ float    g_H2[NN * F];   // h2 (for mean pool)
__device__ float    g_c1p[NN];      // (h2@W3)*dinv
__device__ float    g_c2a[NN];      // scalar edge accumulator
__device__ float    g_c2[NN];       // logits
__device__ float    g_sum16[F];
__device__ unsigned g_maxkey;
__device__ float    g_gmax;
__device__ double   g_sumexp;
__device__ int      g_cmode;        // 0=int32, 1=float32, 2=bool8

// ---------------- helpers ----------------
__device__ __forceinline__ unsigned fkey(float f) {
    unsigned u = __float_as_uint(f);
    return (u & 0x80000000u) ? ~u : (u | 0x80000000u);
}
__device__ __forceinline__ float fdec(unsigned k) {
    unsigned u = (k & 0x80000000u) ? (k ^ 0x80000000u) : ~k;
    return __uint_as_float(u);
}
__device__ __forceinline__ bool chosen(const void* p, int i) {
    int m = g_cmode;
    if (m == 0) return ((const int*)p)[i] != 0;
    if (m == 1) return ((const float*)p)[i] != 0.0f;
    return ((const unsigned char*)p)[i] != 0;
}
__device__ __forceinline__ void red_add_v4(float* p, float4 v) {
    asm volatile("red.global.add.v4.f32 [%0], {%1, %2, %3, %4};"
                 :: "l"(p), "f"(v.x), "f"(v.y), "f"(v.z), "f"(v.w) : "memory");
}

// ---------------- kernels ----------------
// zero everything in one pass
__global__ void k_setup(int n) {
    int idx = blockIdx.x * blockDim.x + threadIdx.x;
    if (idx < n * F) { g_B1[idx] = 0.0f; g_B2[idx] = 0.0f; }
    if (idx < n) { g_cnt[idx] = 0; g_c2a[idx] = 0.0f; }
    if (idx < F) g_sum16[idx] = 0.0f;
    if (idx == 0) { g_maxkey = 0u; g_sumexp = 0.0; }
}

__global__ void k_detect(const unsigned int* __restrict__ w, int nw) {
    __shared__ int notI, notF;
    if (threadIdx.x == 0) { notI = 0; notF = 0; }
    __syncthreads();
    int li = 0, lf = 0;
    for (int i = threadIdx.x; i < nw; i += blockDim.x) {
        unsigned v = w[i];
        li |= (v > 1u);
        lf |= (v != 0u && v != 0x3F800000u);
    }
    if (li) notI = 1;
    if (lf) notF = 1;
    __syncthreads();
    if (threadIdx.x == 0) g_cmode = (!notI) ? 0 : ((!notF) ? 1 : 2);
}

__global__ void k_deg(const int* __restrict__ col, int e) {
    int i = blockIdx.x * blockDim.x + threadIdx.x;
    if (i < e) atomicAdd(&g_cnt[col[i]], 1);
}

// dinv + P1 = (x @ W1) * dinv
__global__ void k_xw1p(const float* __restrict__ x, const float* __restrict__ W1, int n) {
    int idx = blockIdx.x * blockDim.x + threadIdx.x;
    if (idx >= n * F) return;
    int i = idx >> 4, f = idx & 15;
    float di = rsqrtf((float)g_cnt[i] + 2.0f);
    if (f == 0) g_dinv[i] = di;
    float v = x[i * 3 + 0] * __ldg(&W1[0 * F + f])
            + x[i * 3 + 1] * __ldg(&W1[1 * F + f])
            + x[i * 3 + 2] * __ldg(&W1[2 * F + f]);
    g_P1[idx] = v * di;
}

// B[c] += P[r]; 4 threads/edge, one red.v4 each.  LAYER selects globals
// at compile time (no device symbols cross the host launch boundary).
template <int LAYER>
__global__ void k_scatter16(const int* __restrict__ row, const int* __restrict__ col, int e) {
    int gid = blockIdx.x * blockDim.x + threadIdx.x;
    int ed = gid >> 2;
    if (ed >= e) return;
    int q = gid & 3;
    int r = __ldg(&row[ed]);
    int c = __ldg(&col[ed]);
    const float* P = (LAYER == 1) ? g_P1 : g_P2;
    float*       B = (LAYER == 1) ? g_B1 : g_B2;
    float4 v = *(const float4*)&P[r * F + q * 4];
    red_add_v4(&B[c * F + q * 4], v);
}

// h1 = relu(di*B1 + 2di*P1 + b1)  [smem tile] ; P2 = (h1 @ W2) * di
__global__ void k_combdense(const float* __restrict__ b1, const float* __restrict__ W2, int n) {
    __shared__ float sH[16 * 17];
    __shared__ float sW[256];
    int tid = threadIdx.x;
    sW[tid] = W2[tid];
    int il = tid >> 4, f = tid & 15;
    int i = blockIdx.x * 16 + il;
    int idx = i * F + f;
    float di = 0.0f;
    if (i < n) {
        di = g_dinv[i];
        float hv = fmaxf(di * g_B1[idx] + 2.0f * di * g_P1[idx] + __ldg(&b1[f]), 0.0f);
        sH[il * 17 + f] = hv;
    }
    __syncthreads();
    if (i < n) {
        float acc = 0.0f;
#pragma unroll
        for (int k = 0; k < F; k++) acc += sH[il * 17 + k] * sW[k * F + f];
        g_P2[idx] = acc * di;
    }
}

// h2 = relu(di*B2 + 2di*P2 + b2) -> g_H2 ; c1p = (h2 @ W3) * di
__global__ void k_combine2(const float* __restrict__ b2, const float* __restrict__ W3, int n) {
    __shared__ float sW3[16];
    int tid = threadIdx.x;
    if (tid < 16) sW3[tid] = W3[tid];
    __syncthreads();
    int il = tid >> 4, f = tid & 15;
    int i = blockIdx.x * 16 + il;
    int idx = i * F + f;
    float v = 0.0f, di = 0.0f;
    if (i < n) {
        di = g_dinv[i];
        float hv = fmaxf(di * g_B2[idx] + 2.0f * di * g_P2[idx] + __ldg(&b2[f]), 0.0f);
        g_H2[idx] = hv;
        v = hv * sW3[f];
    }
#pragma unroll
    for (int o = 8; o; o >>= 1) v += __shfl_down_sync(0xFFFFFFFFu, v, o, 16);
    if (i < n && f == 0) g_c1p[i] = v * di;
}

__global__ void k_scatter1(const int* __restrict__ row, const int* __restrict__ col, int e) {
    int ed = blockIdx.x * blockDim.x + threadIdx.x;
    if (ed >= e) return;
    atomicAdd(&g_c2a[__ldg(&col[ed])], g_c1p[__ldg(&row[ed])]);
}

// logits = di*c2a + 2di*c1p + b3 ; masked max ; column sums of h2
__global__ void k_reduce1(const void* __restrict__ ch, const float* __restrict__ b3, int n) {
    int idx = blockIdx.x * blockDim.x + threadIdx.x;
    int stride = gridDim.x * blockDim.x;  // multiple of 16
    float sacc = 0.0f;
    for (int j = idx; j < n * F; j += stride) sacc += g_H2[j];
    sacc += __shfl_down_sync(0xFFFFFFFFu, sacc, 16);
    if ((threadIdx.x & 31) < 16) atomicAdd(&g_sum16[idx & 15], sacc);

    float b3v = __ldg(&b3[0]);
    float lmax = -3.0e38f;
    for (int i = idx; i < n; i += stride) {
        float di = g_dinv[i];
        float c2 = di * g_c2a[i] + 2.0f * di * g_c1p[i] + b3v;
        g_c2[i] = c2;
        if (chosen(ch, i)) lmax = fmaxf(lmax, c2);
    }
#pragma unroll
    for (int o = 16; o; o >>= 1) lmax = fmaxf(lmax, __shfl_down_sync(0xFFFFFFFFu, lmax, o));
    if ((threadIdx.x & 31) == 0) atomicMax(&g_maxkey, fkey(lmax));
}

__global__ void k_fin1(float* out, const float* __restrict__ fc_w,
                       const float* __restrict__ fc_b, int n, int out_size) {
    int t = threadIdx.x;
    float p = 0.0f;
    if (t < F) p = (g_sum16[t] / (float)n) * __ldg(&fc_w[t]);
#pragma unroll
    for (int o = 8; o; o >>= 1) p += __shfl_down_sync(0xFFFFFFFFu, p, o);
    if (t == 0) {
        g_gmax = fdec(g_maxkey);
        if (out_size > n) out[n] = p + __ldg(&fc_b[0]);
    }
}

__global__ void k_sumexp(const void* __restrict__ ch, int n) {
    int idx = blockIdx.x * blockDim.x + threadIdx.x;
    int stride = gridDim.x * blockDim.x;
    float gmax = g_gmax;
    double ls = 0.0;
    for (int i = idx; i < n; i += stride)
        if (chosen(ch, i)) ls += (double)expf(g_c2[i] - gmax);
#pragma unroll
    for (int o = 16; o; o >>= 1) ls += __shfl_down_sync(0xFFFFFFFFu, ls, o);
    if ((threadIdx.x & 31) == 0) atomicAdd(&g_sumexp, ls);
}

__global__ void k_writeout(float* __restrict__ out, const void* __restrict__ ch, int n) {
    int i = blockIdx.x * blockDim.x + threadIdx.x;
    if (i >= n) return;
    float v = 0.0f;
    if (chosen(ch, i)) v = expf(g_c2[i] - g_gmax) / (float)g_sumexp;
    out[i] = v;
}

// ---------------- launch ----------------
extern "C" void kernel_launch(void* const* d_in, const int* in_sizes, int n_in,
                              void* d_out, int out_size) {
    const float* x    = (const float*)d_in[0];
    const int*   ei   = (const int*)d_in[1];
    const void*  ch   = (const void*)d_in[2];
    const float* W1   = (const float*)d_in[3];
    const float* b1   = (const float*)d_in[4];
    const float* W2   = (const float*)d_in[5];
    const float* b2   = (const float*)d_in[6];
    const float* W3   = (const float*)d_in[7];
    const float* b3   = (const float*)d_in[8];
    const float* fc_w = (const float*)d_in[9];
    const float* fc_b = (const float*)d_in[10];
    float* out = (float*)d_out;

    int n = in_sizes[0] / 3;
    int e = in_sizes[1] / 2;
    if (n > NN) n = NN;
    if (e > EE) e = EE;
    const int* row = ei;       // edge_index[0] = source
    const int* col = ei + e;   // edge_index[1] = target

    int bn   = (n + 255) / 256;
    int be   = (e + 255) / 256;
    int bnf  = (n * F + 255) / 256;
    int bag  = (n + 15) / 16;                          // 16 nodes / 256-thread block
    int bs4  = (int)(((long long)e * 4 + 255) / 256);  // 4 threads per edge

    k_setup<<<bnf, 256>>>(n);
    k_detect<<<1, 256>>>((const unsigned int*)ch, n / 4);
    k_deg<<<be, 256>>>(col, e);

    k_xw1p<<<bnf, 256>>>(x, W1, n);
    k_scatter16<1><<<bs4, 256>>>(row, col, e);
    k_combdense<<<bag, 256>>>(b1, W2, n);
    k_scatter16<2><<<bs4, 256>>>(row, col, e);
    k_combine2<<<bag, 256>>>(b2, W3, n);

    k_scatter1<<<be, 256>>>(row, col, e);
    k_reduce1<<<512, 256>>>(ch, b3, n);
    k_fin1<<<1, 32>>>(out, fc_w, fc_b, n, out_size);
    k_sumexp<<<512, 256>>>(ch, n);
    k_writeout<<<bn, 256>>>(out, ch, n);
}